// round 1
// baseline (speedup 1.0000x reference)
#include <cuda_runtime.h>

#define NMAX 100000
#define EMAX 1600000

// ---- scratch (device globals: no allocation allowed) ----
__device__ float4 g_feat4[NMAX * 16];   // per-node 64-float feature row
__device__ float4 g_num4[NMAX * 16];    // per-node 64-float numerator row
__device__ float  g_aux[NMAX * 8];      // layer1: a_src[4] | a_dst[4]
__device__ float  g_denom[NMAX * 4];    // softmax denominators (up to 4 heads)
__device__ int    g_src[EMAX];
__device__ int    g_dst[EMAX];
__device__ int    g_is64;

__device__ __forceinline__ void red_add_v4(float* addr, float a, float b, float c, float d) {
    asm volatile("red.global.add.v4.f32 [%0], {%1,%2,%3,%4};"
                 :: "l"(addr), "f"(a), "f"(b), "f"(c), "f"(d) : "memory");
}

__device__ __forceinline__ float lrelu(float v) { return v > 0.f ? v : 0.2f * v; }

// ---- edge dtype detection + conversion ----
__global__ void detect_kernel(const unsigned* __restrict__ w, int e) {
    int cnt = e < 64 ? e : 64;
    int is64 = 1;
    for (int i = 0; i < cnt; i++)
        if (w[2 * i + 1] != 0u) { is64 = 0; break; }
    g_is64 = is64;
}

__global__ void convert_kernel(const void* __restrict__ p, int e) {
    int i = blockIdx.x * blockDim.x + threadIdx.x;
    if (i >= e) return;
    if (g_is64) {
        const long long* q = (const long long*)p;
        g_src[i] = (int)q[i];
        g_dst[i] = (int)q[(long long)e + i];
    } else {
        const int* q = (const int*)p;
        g_src[i] = q[i];
        g_dst[i] = q[e + i];
    }
}

// ---- layer 1 node pre-pass: h = x@W1, a_src/a_dst, zero accumulators ----
__global__ __launch_bounds__(256) void node1_kernel(
    const float* __restrict__ x, const float* __restrict__ W1,
    const float* __restrict__ asrc, const float* __restrict__ adst, int n) {
    int t = blockIdx.x * blockDim.x + threadIdx.x;
    int node = t >> 6;
    int c = t & 63;
    if (node >= n) return;   // warp (32 thr) lies fully inside one node's 64-thread group
    float x0 = x[node * 3 + 0], x1 = x[node * 3 + 1], x2 = x[node * 3 + 2];
    float h = x0 * W1[c] + x1 * W1[64 + c] + x2 * W1[128 + c];
    ((float*)g_feat4)[node * 64 + c] = h;
    ((float*)g_num4)[node * 64 + c] = 0.f;
    if (c < 4) g_denom[node * 4 + c] = 0.f;
    float ps = h * asrc[c];
    float pd = h * adst[c];
    #pragma unroll
    for (int o = 8; o >= 1; o >>= 1) {
        ps += __shfl_xor_sync(0xffffffffu, ps, o);
        pd += __shfl_xor_sync(0xffffffffu, pd, o);
    }
    if ((c & 15) == 0) {
        int hh = c >> 4;
        g_aux[node * 8 + hh]     = ps;
        g_aux[node * 8 + 4 + hh] = pd;
    }
}

// ---- layer 1 edge pass: 16 lanes per edge ----
__global__ __launch_bounds__(256) void edge1_kernel(int e, int m) {
    int gt = blockIdx.x * blockDim.x + threadIdx.x;
    int edge = gt >> 4;
    int l = gt & 15;
    if (edge >= m) return;  // no shfl here, early exit safe
    int s, d;
    if (edge < e) { s = g_src[edge]; d = g_dst[edge]; }
    else          { s = d = edge - e; }
    int h = l >> 2;
    float a = g_aux[s * 8 + h] + g_aux[d * 8 + 4 + h];
    float ex = __expf(lrelu(a));
    float4 f = g_feat4[s * 16 + l];
    red_add_v4(((float*)g_num4) + d * 64 + l * 4, ex * f.x, ex * f.y, ex * f.z, ex * f.w);
    if ((l & 3) == 0) atomicAdd(&g_denom[d * 4 + h], ex);
}

// ---- layer 1 finish + layer 2 node pre-pass ----
__global__ __launch_bounds__(256) void node1b_kernel(
    const float* __restrict__ b1,
    const float* __restrict__ W2l, const float* __restrict__ b2l,
    const float* __restrict__ W2r, const float* __restrict__ b2r, int n) {
    __shared__ float sx[256];               // 4 nodes * 64
    int t = threadIdx.x;
    int node = blockIdx.x * 4 + (t >> 6);
    int c = t & 63;
    bool valid = node < n;
    float x1v = 0.f;
    if (valid) {
        float num = ((float*)g_num4)[node * 64 + c];
        float den = g_denom[node * 4 + (c >> 4)];
        x1v = fmaxf(num / (den + 1e-16f) + b1[c], 0.f);
    }
    sx[t] = x1v;
    __syncthreads();
    if (!valid) return;
    if (c < 32) ((float*)g_num4)[node * 64 + c] = 0.f;  // num2 accumulator
    if (c < 2)  g_denom[node * 4 + c] = 0.f;
    const float* sxn = sx + (t & ~63);
    int col = c & 31;
    const float* W = (c < 32) ? W2l : W2r;
    float acc = (c < 32) ? b2l[col] : b2r[col];
    #pragma unroll 8
    for (int k = 0; k < 64; k++) acc += sxn[k] * W[k * 32 + col];
    ((float*)g_feat4)[node * 64 + c] = acc;  // hl | hr
}

// ---- layer 2 edge pass: 8 lanes per edge ----
__global__ __launch_bounds__(256) void edge2_kernel(const float* __restrict__ att2, int e, int m) {
    int gt = blockIdx.x * blockDim.x + threadIdx.x;
    int edge = gt >> 3;
    int l = gt & 7;
    bool valid = edge < m;
    int s = 0, d = 0;
    if (valid) {
        if (edge < e) { s = g_src[edge]; d = g_dst[edge]; }
        else          { s = d = edge - e; }
    }
    int h = l >> 2;
    int q = l & 3;                        // quad index: 4 floats each
    float4 hl = g_feat4[s * 16 + h * 4 + q];
    float4 hr = g_feat4[d * 16 + 8 + h * 4 + q];
    int ai = h * 16 + q * 4;
    float p = lrelu(hl.x + hr.x) * att2[ai]
            + lrelu(hl.y + hr.y) * att2[ai + 1]
            + lrelu(hl.z + hr.z) * att2[ai + 2]
            + lrelu(hl.w + hr.w) * att2[ai + 3];
    p += __shfl_xor_sync(0xffffffffu, p, 1);
    p += __shfl_xor_sync(0xffffffffu, p, 2);
    if (!valid) return;
    float ex = __expf(p);
    red_add_v4(((float*)g_num4) + d * 64 + h * 16 + q * 4,
               ex * hl.x, ex * hl.y, ex * hl.z, ex * hl.w);
    if (q == 0) atomicAdd(&g_denom[d * 4 + h], ex);
}

// ---- layer 2 finish + layer 3 node pre-pass (q,k,v,skip) ----
__global__ __launch_bounds__(256) void node2_kernel(
    const float* __restrict__ b2,
    const float* __restrict__ Wq, const float* __restrict__ bq,
    const float* __restrict__ Wk, const float* __restrict__ bk,
    const float* __restrict__ Wv, const float* __restrict__ bv,
    const float* __restrict__ Ws, const float* __restrict__ bs, int n) {
    __shared__ float sx[256];               // 8 nodes * 32
    int t = threadIdx.x;
    int node = blockIdx.x * 8 + (t >> 5);
    int c = t & 31;
    bool valid = node < n;
    float x2v = 0.f;
    if (valid) {
        float num = ((float*)g_num4)[node * 64 + c];
        float den = g_denom[node * 4 + (c >> 4)];
        x2v = num / (den + 1e-16f) + b2[c];
    }
    sx[t] = x2v;
    __syncthreads();
    if (!valid) return;
    if (c < 8) ((float*)g_num4)[node * 64 + c] = 0.f;   // num3 accumulator (cols 0..7)
    if (c == 0) g_denom[node * 4] = 0.f;
    const float* sxn = sx + (t & ~31);
    float* frow = ((float*)g_feat4) + node * 64;
    if (c < 28) {
        int mat = c / 7, col = c % 7;
        const float* W; const float* b; int off;
        if (mat == 0)      { W = Ws; b = bs; off = 0;  }  // skip
        else if (mat == 1) { W = Wq; b = bq; off = 8;  }
        else if (mat == 2) { W = Wk; b = bk; off = 16; }
        else               { W = Wv; b = bv; off = 24; }
        float acc = b[col];
        #pragma unroll 8
        for (int k = 0; k < 32; k++) acc += sxn[k] * W[k * 7 + col];
        frow[off + col] = acc;
    } else if (c == 28) {
        frow[7]  = 0.f;   // padding so float4 loads are clean zeros
        frow[15] = 0.f;
        frow[23] = 0.f;
        frow[31] = 0.f;
    }
}

// ---- layer 3 edge pass: 1 thread per edge (original edges only) ----
__global__ __launch_bounds__(256) void edge3_kernel(int e) {
    int edge = blockIdx.x * blockDim.x + threadIdx.x;
    if (edge >= e) return;
    int s = g_src[edge], d = g_dst[edge];
    const float4* fq = g_feat4 + (size_t)d * 16;
    const float4* fk = g_feat4 + (size_t)s * 16;
    float4 q0 = fq[2], q1 = fq[3];       // q at +8..14, +15=0
    float4 k0 = fk[4], k1 = fk[5];       // k at +16..22, +23=0
    float dot = q0.x * k0.x + q0.y * k0.y + q0.z * k0.z + q0.w * k0.w
              + q1.x * k1.x + q1.y * k1.y + q1.z * k1.z;
    float ex = __expf(dot * 0.3779644730092272f);   // 1/sqrt(7)
    float4 v0 = fk[6], v1 = fk[7];       // v at +24..30, +31=0
    float* np = ((float*)g_num4) + (size_t)d * 64;
    red_add_v4(np,     ex * v0.x, ex * v0.y, ex * v0.z, ex * v0.w);
    red_add_v4(np + 4, ex * v1.x, ex * v1.y, ex * v1.z, ex * v1.w);
    atomicAdd(&g_denom[d * 4], ex);
}

// ---- final: out = num3/denom3 + skip ----
__global__ __launch_bounds__(256) void final_kernel(float* __restrict__ out, int n) {
    int t = blockIdx.x * blockDim.x + threadIdx.x;
    if (t >= n * 7) return;
    int node = t / 7, c = t % 7;
    float num = ((float*)g_num4)[node * 64 + c];
    float den = g_denom[node * 4];
    out[t] = num / (den + 1e-16f) + ((float*)g_feat4)[node * 64 + c];
}

extern "C" void kernel_launch(void* const* d_in, const int* in_sizes, int n_in,
                              void* d_out, int out_size) {
    const float* x     = (const float*)d_in[0];
    const void*  eidx  = d_in[1];
    const float* W1    = (const float*)d_in[2];
    const float* asrc  = (const float*)d_in[3];
    const float* adst  = (const float*)d_in[4];
    const float* b1    = (const float*)d_in[5];
    const float* W2l   = (const float*)d_in[6];
    const float* b2l   = (const float*)d_in[7];
    const float* W2r   = (const float*)d_in[8];
    const float* b2r   = (const float*)d_in[9];
    const float* att2  = (const float*)d_in[10];
    const float* b2    = (const float*)d_in[11];
    const float* Wq    = (const float*)d_in[12];
    const float* bq    = (const float*)d_in[13];
    const float* Wk    = (const float*)d_in[14];
    const float* bk    = (const float*)d_in[15];
    const float* Wv    = (const float*)d_in[16];
    const float* bv    = (const float*)d_in[17];
    const float* Ws    = (const float*)d_in[18];
    const float* bs    = (const float*)d_in[19];
    float* out = (float*)d_out;

    int n = in_sizes[0] / 3;
    int e = in_sizes[1] / 2;
    if (n > NMAX) n = NMAX;
    if (e > EMAX) e = EMAX;
    int m = e + n;   // edges with self-loops (layers 1 & 2)

    detect_kernel<<<1, 1>>>((const unsigned*)eidx, e);
    convert_kernel<<<(e + 255) / 256, 256>>>(eidx, e);

    node1_kernel<<<(n * 64 + 255) / 256, 256>>>(x, W1, asrc, adst, n);
    edge1_kernel<<<((long long)m * 16 + 255) / 256, 256>>>(e, m);
    node1b_kernel<<<(n + 3) / 4, 256>>>(b1, W2l, b2l, W2r, b2r, n);
    edge2_kernel<<<((long long)m * 8 + 255) / 256, 256>>>(att2, e, m);
    node2_kernel<<<(n + 7) / 8, 256>>>(b2, Wq, bq, Wk, bk, Wv, bv, Ws, bs, n);
    edge3_kernel<<<(e + 255) / 256, 256>>>(e);
    final_kernel<<<(n * 7 + 255) / 256, 256>>>(out, n);
}

// round 3
// speedup vs baseline: 1.1979x; 1.1979x over previous
#include <cuda_runtime.h>

#define NMAX 100000
#define EMAX 1600000

// ---- scratch (device globals: no allocation allowed) ----
__device__ float4 g_feat4[NMAX * 16];     // per-node 64-float feature row
__device__ float4 g_num4[NMAX * 16];      // x1 (64f) then x2 (32f) storage
__device__ float  g_aux[NMAX * 8];        // layer1: a_src[4] | a_dst[4]
__device__ int    g_es[EMAX];             // raw src
__device__ int    g_ed[EMAX];             // raw dst
__device__ int    g_srt[EMAX + NMAX];     // CSR: in-neighbor src ids, self at head
__device__ int    g_cnt[NMAX];
__device__ int    g_off[NMAX + 1];
__device__ int    g_cur[NMAX];
__device__ int    g_part[256];
__device__ int    g_is64;

__device__ __forceinline__ float lrelu(float v) { return v > 0.f ? v : 0.2f * v; }

// ================= CSR construction =================

__global__ void init_cnt_kernel(int n) {
    int i = blockIdx.x * blockDim.x + threadIdx.x;
    if (i < n) g_cnt[i] = 1;   // self-loop
}

__global__ void detect_kernel(const unsigned* __restrict__ w, int e) {
    int cnt = e < 64 ? e : 64;
    int is64 = 1;
    for (int i = 0; i < cnt; i++)
        if (w[2 * i + 1] != 0u) { is64 = 0; break; }
    g_is64 = is64;
}

__global__ void conv_hist_kernel(const void* __restrict__ p, int e) {
    int i = blockIdx.x * blockDim.x + threadIdx.x;
    if (i >= e) return;
    int s, d;
    if (g_is64) {
        const long long* q = (const long long*)p;
        s = (int)q[i];
        d = (int)q[(long long)e + i];
    } else {
        const int* q = (const int*)p;
        s = q[i];
        d = q[e + i];
    }
    g_es[i] = s;
    g_ed[i] = d;
    atomicAdd(&g_cnt[d], 1);
}

__global__ void scanA_kernel(int n) {          // blockDim 1024
    __shared__ int sh[1024];
    int t = threadIdx.x;
    int i = blockIdx.x * 1024 + t;
    sh[t] = (i < n) ? g_cnt[i] : 0;
    __syncthreads();
    for (int o = 512; o > 0; o >>= 1) {
        if (t < o) sh[t] += sh[t + o];
        __syncthreads();
    }
    if (t == 0) g_part[blockIdx.x] = sh[0];
}

__global__ void scanB_kernel(int nb) {         // 1 thread
    int run = 0;
    for (int b = 0; b < nb; b++) {
        int v = g_part[b];
        g_part[b] = run;
        run += v;
    }
}

__global__ void scanC_kernel(int n) {          // blockDim 1024
    __shared__ int sh[1024];
    int t = threadIdx.x;
    int i = blockIdx.x * 1024 + t;
    int v = (i < n) ? g_cnt[i] : 0;
    sh[t] = v;
    __syncthreads();
    for (int o = 1; o < 1024; o <<= 1) {
        int a = (t >= o) ? sh[t - o] : 0;
        __syncthreads();
        sh[t] += a;
        __syncthreads();
    }
    int excl = sh[t] - v + g_part[blockIdx.x];
    if (i < n) {
        g_off[i] = excl;
        g_cur[i] = excl + 1;
        g_srt[excl] = i;   // self at segment head
    }
    if (i == n - 1) g_off[n] = excl + v;
}

__global__ void scatter_kernel(int e) {
    int i = blockIdx.x * blockDim.x + threadIdx.x;
    if (i >= e) return;
    int d = g_ed[i];
    int pos = atomicAdd(&g_cur[d], 1);
    g_srt[pos] = g_es[i];
}

// ================= layer 1 =================

__global__ __launch_bounds__(256) void node1_kernel(
    const float* __restrict__ x, const float* __restrict__ W1,
    const float* __restrict__ asrc, const float* __restrict__ adst, int n) {
    int t = blockIdx.x * blockDim.x + threadIdx.x;
    int node = t >> 6;
    int c = t & 63;
    if (node >= n) return;
    float x0 = x[node * 3 + 0], x1 = x[node * 3 + 1], x2 = x[node * 3 + 2];
    float h = x0 * W1[c] + x1 * W1[64 + c] + x2 * W1[128 + c];
    ((float*)g_feat4)[node * 64 + c] = h;
    float ps = h * asrc[c];
    float pd = h * adst[c];
    #pragma unroll
    for (int o = 8; o >= 1; o >>= 1) {
        ps += __shfl_xor_sync(0xffffffffu, ps, o);
        pd += __shfl_xor_sync(0xffffffffu, pd, o);
    }
    if ((c & 15) == 0) {
        int hh = c >> 4;
        g_aux[node * 8 + hh]     = ps;
        g_aux[node * 8 + 4 + hh] = pd;
    }
}

// warp per node; 2 edges in flight (2 x 16 lanes); no in-loop shuffles
__global__ __launch_bounds__(256) void agg1_kernel(const float* __restrict__ b1, int n) {
    int node = (blockIdx.x * 256 + threadIdx.x) >> 5;
    if (node >= n) return;
    int lane = threadIdx.x & 31;
    int half = lane >> 4;
    int l = lane & 15;
    int h = l >> 2;
    float adst = g_aux[node * 8 + 4 + h];
    int beg = g_off[node], end = g_off[node + 1];
    float4 acc = make_float4(0.f, 0.f, 0.f, 0.f);
    float den = 0.f;
    for (int j = beg + half; j < end; j += 2) {
        int s = __ldg(&g_srt[j]);
        float ex = __expf(lrelu(__ldg(&g_aux[s * 8 + h]) + adst));
        float4 f = __ldg(&g_feat4[s * 16 + l]);
        acc.x = fmaf(ex, f.x, acc.x);
        acc.y = fmaf(ex, f.y, acc.y);
        acc.z = fmaf(ex, f.z, acc.z);
        acc.w = fmaf(ex, f.w, acc.w);
        den += ex;
    }
    acc.x += __shfl_xor_sync(0xffffffffu, acc.x, 16);
    acc.y += __shfl_xor_sync(0xffffffffu, acc.y, 16);
    acc.z += __shfl_xor_sync(0xffffffffu, acc.z, 16);
    acc.w += __shfl_xor_sync(0xffffffffu, acc.w, 16);
    den   += __shfl_xor_sync(0xffffffffu, den, 16);
    if (half == 0) {
        float inv = 1.f / (den + 1e-16f);
        float4 bb = ((const float4*)b1)[l];
        float4 r;
        r.x = fmaxf(fmaf(acc.x, inv, bb.x), 0.f);
        r.y = fmaxf(fmaf(acc.y, inv, bb.y), 0.f);
        r.z = fmaxf(fmaf(acc.z, inv, bb.z), 0.f);
        r.w = fmaxf(fmaf(acc.w, inv, bb.w), 0.f);
        g_num4[node * 16 + l] = r;   // x1
    }
}

// GEMV: hl|hr = x1 @ [W2l|W2r] + bias
__global__ __launch_bounds__(256) void node1b_kernel(
    const float* __restrict__ W2l, const float* __restrict__ b2l,
    const float* __restrict__ W2r, const float* __restrict__ b2r, int n) {
    __shared__ float sx[256];               // 4 nodes * 64
    int t = threadIdx.x;
    int node = blockIdx.x * 4 + (t >> 6);
    int c = t & 63;
    bool valid = node < n;
    sx[t] = valid ? ((const float*)g_num4)[node * 64 + c] : 0.f;
    __syncthreads();
    if (!valid) return;
    const float* sxn = sx + (t & ~63);
    int col = c & 31;
    const float* W = (c < 32) ? W2l : W2r;
    float acc = (c < 32) ? b2l[col] : b2r[col];
    #pragma unroll 8
    for (int k = 0; k < 64; k++) acc = fmaf(sxn[k], W[k * 32 + col], acc);
    ((float*)g_feat4)[node * 64 + c] = acc;  // hl | hr
}

// ================= layer 2 =================
// warp per node; 4 edges in flight (4 x 8 lanes)
// In-loop shuffles use PER-GROUP masks: groups iterate different trip counts,
// so a full-warp mask would be UB on the ragged tail (the round-2 bug).
__global__ __launch_bounds__(256) void agg2_kernel(
    const float* __restrict__ att2, const float* __restrict__ b2, int n) {
    int node = (blockIdx.x * 256 + threadIdx.x) >> 5;
    if (node >= n) return;
    int lane = threadIdx.x & 31;
    int grp = lane >> 3;
    int l = lane & 7;
    unsigned gmask = 0xFFu << (grp * 8);
    float4 hr  = __ldg(&g_feat4[node * 16 + 8 + l]);
    float4 att = ((const float4*)att2)[l];
    int beg = g_off[node], end = g_off[node + 1];
    float4 acc = make_float4(0.f, 0.f, 0.f, 0.f);
    float den = 0.f;
    for (int j = beg + grp; j < end; j += 4) {
        int s = __ldg(&g_srt[j]);
        float4 hl = __ldg(&g_feat4[s * 16 + l]);
        float p = lrelu(hl.x + hr.x) * att.x
                + lrelu(hl.y + hr.y) * att.y
                + lrelu(hl.z + hr.z) * att.z
                + lrelu(hl.w + hr.w) * att.w;
        p += __shfl_xor_sync(gmask, p, 1);
        p += __shfl_xor_sync(gmask, p, 2);   // full 16-dim head dot
        float ex = __expf(p);
        acc.x = fmaf(ex, hl.x, acc.x);
        acc.y = fmaf(ex, hl.y, acc.y);
        acc.z = fmaf(ex, hl.z, acc.z);
        acc.w = fmaf(ex, hl.w, acc.w);
        den += ex;
    }
    #pragma unroll
    for (int o = 8; o <= 16; o <<= 1) {
        acc.x += __shfl_xor_sync(0xffffffffu, acc.x, o);
        acc.y += __shfl_xor_sync(0xffffffffu, acc.y, o);
        acc.z += __shfl_xor_sync(0xffffffffu, acc.z, o);
        acc.w += __shfl_xor_sync(0xffffffffu, acc.w, o);
        den   += __shfl_xor_sync(0xffffffffu, den, o);
    }
    if (grp == 0) {
        float inv = 1.f / (den + 1e-16f);
        float4 bb = ((const float4*)b2)[l];
        float4 r;
        r.x = fmaf(acc.x, inv, bb.x);
        r.y = fmaf(acc.y, inv, bb.y);
        r.z = fmaf(acc.z, inv, bb.z);
        r.w = fmaf(acc.w, inv, bb.w);
        g_num4[node * 16 + l] = r;   // x2 (32 floats)
    }
}

// GEMVs for layer 3: skip | q | k | v into feat row (offsets 0,8,16,24; pads zeroed)
__global__ __launch_bounds__(256) void node2_kernel(
    const float* __restrict__ Wq, const float* __restrict__ bq,
    const float* __restrict__ Wk, const float* __restrict__ bk,
    const float* __restrict__ Wv, const float* __restrict__ bv,
    const float* __restrict__ Ws, const float* __restrict__ bs, int n) {
    __shared__ float sx[256];               // 8 nodes * 32
    int t = threadIdx.x;
    int node = blockIdx.x * 8 + (t >> 5);
    int c = t & 31;
    bool valid = node < n;
    sx[t] = valid ? ((const float*)g_num4)[node * 64 + c] : 0.f;
    __syncthreads();
    if (!valid) return;
    const float* sxn = sx + (t & ~31);
    float* frow = ((float*)g_feat4) + (size_t)node * 64;
    if (c < 28) {
        int mat = c / 7, col = c % 7;
        const float* W; const float* b; int off;
        if (mat == 0)      { W = Ws; b = bs; off = 0;  }
        else if (mat == 1) { W = Wq; b = bq; off = 8;  }
        else if (mat == 2) { W = Wk; b = bk; off = 16; }
        else               { W = Wv; b = bv; off = 24; }
        float acc = b[col];
        #pragma unroll 8
        for (int k = 0; k < 32; k++) acc = fmaf(sxn[k], W[k * 7 + col], acc);
        frow[off + col] = acc;
    } else if (c == 28) {
        frow[7]  = 0.f;
        frow[15] = 0.f;
        frow[23] = 0.f;
        frow[31] = 0.f;
    }
}

// ================= layer 3 (fused final) =================
// warp per node; 4 edges in flight (4 x 8 lanes); skips self entry
// In-loop dot reduction uses per-group mask (see agg2 comment).
__global__ __launch_bounds__(256) void agg3_kernel(float* __restrict__ out, int n) {
    int node = (blockIdx.x * 256 + threadIdx.x) >> 5;
    if (node >= n) return;
    int lane = threadIdx.x & 31;
    int grp = lane >> 3;
    int c = lane & 7;
    unsigned gmask = 0xFFu << (grp * 8);
    const float* frow = ((const float*)g_feat4) + (size_t)node * 64;
    float qv = __ldg(&frow[8 + c]);
    int beg = g_off[node] + 1;   // skip self (TransformerConv: no self-loops)
    int end = g_off[node + 1];
    float acc = 0.f, den = 0.f;
    for (int j = beg + grp; j < end; j += 4) {
        int s = __ldg(&g_srt[j]);
        const float* fs = ((const float*)g_feat4) + (size_t)s * 64;
        float kv = __ldg(&fs[16 + c]);
        float vv = __ldg(&fs[24 + c]);
        float p = qv * kv;
        p += __shfl_xor_sync(gmask, p, 1);
        p += __shfl_xor_sync(gmask, p, 2);
        p += __shfl_xor_sync(gmask, p, 4);   // dot over 8 dims (pad=0)
        float ex = __expf(p * 0.3779644730092272f);  // 1/sqrt(7)
        acc = fmaf(ex, vv, acc);
        den += ex;
    }
    acc += __shfl_xor_sync(0xffffffffu, acc, 8);
    den += __shfl_xor_sync(0xffffffffu, den, 8);
    acc += __shfl_xor_sync(0xffffffffu, acc, 16);
    den += __shfl_xor_sync(0xffffffffu, den, 16);
    if (grp == 0 && c < 7)
        out[node * 7 + c] = acc / (den + 1e-16f) + frow[c];
}

// ================= launch =================

extern "C" void kernel_launch(void* const* d_in, const int* in_sizes, int n_in,
                              void* d_out, int out_size) {
    const float* x     = (const float*)d_in[0];
    const void*  eidx  = d_in[1];
    const float* W1    = (const float*)d_in[2];
    const float* asrc  = (const float*)d_in[3];
    const float* adst  = (const float*)d_in[4];
    const float* b1    = (const float*)d_in[5];
    const float* W2l   = (const float*)d_in[6];
    const float* b2l   = (const float*)d_in[7];
    const float* W2r   = (const float*)d_in[8];
    const float* b2r   = (const float*)d_in[9];
    const float* att2  = (const float*)d_in[10];
    const float* b2    = (const float*)d_in[11];
    const float* Wq    = (const float*)d_in[12];
    const float* bq    = (const float*)d_in[13];
    const float* Wk    = (const float*)d_in[14];
    const float* bk    = (const float*)d_in[15];
    const float* Wv    = (const float*)d_in[16];
    const float* bv    = (const float*)d_in[17];
    const float* Ws    = (const float*)d_in[18];
    const float* bs    = (const float*)d_in[19];
    float* out = (float*)d_out;

    int n = in_sizes[0] / 3;
    int e = in_sizes[1] / 2;
    if (n > NMAX) n = NMAX;
    if (e > EMAX) e = EMAX;
    int nb = (n + 1023) / 1024;

    // CSR build
    init_cnt_kernel<<<(n + 255) / 256, 256>>>(n);
    detect_kernel<<<1, 1>>>((const unsigned*)eidx, e);
    conv_hist_kernel<<<(e + 255) / 256, 256>>>(eidx, e);
    scanA_kernel<<<nb, 1024>>>(n);
    scanB_kernel<<<1, 1>>>(nb);
    scanC_kernel<<<nb, 1024>>>(n);
    scatter_kernel<<<(e + 255) / 256, 256>>>(e);

    int aggBlocks = (n * 32 + 255) / 256;
    // layer 1
    node1_kernel<<<(n * 64 + 255) / 256, 256>>>(x, W1, asrc, adst, n);
    agg1_kernel<<<aggBlocks, 256>>>(b1, n);
    node1b_kernel<<<(n + 3) / 4, 256>>>(W2l, b2l, W2r, b2r, n);
    // layer 2
    agg2_kernel<<<aggBlocks, 256>>>(att2, b2, n);
    node2_kernel<<<(n + 7) / 8, 256>>>(Wq, bq, Wk, bk, Wv, bv, Ws, bs, n);
    // layer 3 + final
    agg3_kernel<<<aggBlocks, 256>>>(out, n);
}

// round 4
// speedup vs baseline: 1.2229x; 1.0208x over previous
#include <cuda_runtime.h>

#define NMAX 100000
#define EMAX 1600000

// ---- scratch (device globals: no allocation allowed) ----
__device__ float4 g_feat4[NMAX * 16];     // per-node 64-float feature row
__device__ float4 g_num4[NMAX * 16];      // x1 (64f) then x2 (32f) storage
__device__ float  g_aux[NMAX * 8];        // layer1: a_src[4] | a_dst[4]
__device__ int    g_es[EMAX];             // raw src
__device__ int    g_ed[EMAX];             // raw dst
__device__ int    g_srt[EMAX + NMAX];     // CSR: in-neighbor src ids, self at head
__device__ int    g_cnt[NMAX];            // zero at entry; reset by scanC each call
__device__ int    g_off[NMAX + 1];
__device__ int    g_cur[NMAX];
__device__ int    g_part[256];
__device__ int    g_is64;

__device__ __forceinline__ float lrelu(float v) { return v > 0.f ? v : 0.2f * v; }

// ================= CSR construction =================

__global__ void detect_kernel(const unsigned* __restrict__ w, int e) {
    int cnt = e < 64 ? e : 64;
    int is64 = 1;
    for (int i = 0; i < cnt; i++)
        if (w[2 * i + 1] != 0u) { is64 = 0; break; }
    g_is64 = is64;
}

__global__ void conv_hist_kernel(const void* __restrict__ p, int e) {
    int i = blockIdx.x * blockDim.x + threadIdx.x;
    if (i >= e) return;
    int s, d;
    if (g_is64) {
        const long long* q = (const long long*)p;
        s = (int)q[i];
        d = (int)q[(long long)e + i];
    } else {
        const int* q = (const int*)p;
        s = q[i];
        d = q[e + i];
    }
    g_es[i] = s;
    g_ed[i] = d;
    atomicAdd(&g_cnt[d], 1);
}

__global__ void scanA_kernel(int n) {          // blockDim 1024: per-block sums
    __shared__ int sh[1024];
    int t = threadIdx.x;
    int i = blockIdx.x * 1024 + t;
    sh[t] = (i < n) ? g_cnt[i] + 1 : 0;        // +1: self-loop
    __syncthreads();
    for (int o = 512; o > 0; o >>= 1) {
        if (t < o) sh[t] += sh[t + o];
        __syncthreads();
    }
    if (t == 0) g_part[blockIdx.x] = sh[0];
}

__global__ void scanB_kernel(int nb) {         // 1 block, 128 threads: exclusive scan of partials
    __shared__ int sh[128];
    int t = threadIdx.x;
    int v = (t < nb) ? g_part[t] : 0;
    sh[t] = v;
    __syncthreads();
    #pragma unroll
    for (int o = 1; o < 128; o <<= 1) {
        int a = (t >= o) ? sh[t - o] : 0;
        __syncthreads();
        sh[t] += a;
        __syncthreads();
    }
    if (t < nb) g_part[t] = sh[t] - v;
}

__global__ void scanC_kernel(int n) {          // blockDim 1024: offsets + self at head + reset cnt
    __shared__ int sh[1024];
    int t = threadIdx.x;
    int i = blockIdx.x * 1024 + t;
    int v = (i < n) ? g_cnt[i] + 1 : 0;
    sh[t] = v;
    __syncthreads();
    for (int o = 1; o < 1024; o <<= 1) {
        int a = (t >= o) ? sh[t - o] : 0;
        __syncthreads();
        sh[t] += a;
        __syncthreads();
    }
    int excl = sh[t] - v + g_part[blockIdx.x];
    if (i < n) {
        g_off[i] = excl;
        g_cur[i] = excl + 1;
        g_srt[excl] = i;   // self at segment head
        g_cnt[i] = 0;      // leave zeroed for next call (deterministic across replays)
    }
    if (i == n - 1) g_off[n] = excl + v;
}

__global__ void scatter_kernel(int e) {
    int i = blockIdx.x * blockDim.x + threadIdx.x;
    if (i >= e) return;
    int d = g_ed[i];
    int pos = atomicAdd(&g_cur[d], 1);
    g_srt[pos] = g_es[i];
}

// ================= layer 1 =================

__global__ __launch_bounds__(256) void node1_kernel(
    const float* __restrict__ x, const float* __restrict__ W1,
    const float* __restrict__ asrc, const float* __restrict__ adst, int n) {
    int t = blockIdx.x * blockDim.x + threadIdx.x;
    int node = t >> 6;
    int c = t & 63;
    if (node >= n) return;
    float x0 = x[node * 3 + 0], x1 = x[node * 3 + 1], x2 = x[node * 3 + 2];
    float h = x0 * W1[c] + x1 * W1[64 + c] + x2 * W1[128 + c];
    ((float*)g_feat4)[node * 64 + c] = h;
    float ps = h * asrc[c];
    float pd = h * adst[c];
    #pragma unroll
    for (int o = 8; o >= 1; o >>= 1) {
        ps += __shfl_xor_sync(0xffffffffu, ps, o);
        pd += __shfl_xor_sync(0xffffffffu, pd, o);
    }
    if ((c & 15) == 0) {
        int hh = c >> 4;
        g_aux[node * 8 + hh]     = ps;
        g_aux[node * 8 + 4 + hh] = pd;
    }
}

// warp per node; 16 lanes per edge (2 groups), software-pipelined unroll-2
__global__ __launch_bounds__(256) void agg1_kernel(const float* __restrict__ b1, int n) {
    int node = (blockIdx.x * 256 + threadIdx.x) >> 5;
    if (node >= n) return;
    int lane = threadIdx.x & 31;
    int half = lane >> 4;
    int l = lane & 15;
    int h = l >> 2;
    float adst = g_aux[node * 8 + 4 + h];
    int beg = g_off[node], end = g_off[node + 1];
    float4 acc = make_float4(0.f, 0.f, 0.f, 0.f);
    float den = 0.f;
    int j = beg + half;
    for (; j + 2 < end; j += 4) {               // two independent edges per group
        int s0 = __ldg(&g_srt[j]);
        int s1 = __ldg(&g_srt[j + 2]);
        float a0 = __ldg(&g_aux[s0 * 8 + h]);
        float a1 = __ldg(&g_aux[s1 * 8 + h]);
        float4 f0 = __ldg(&g_feat4[s0 * 16 + l]);
        float4 f1 = __ldg(&g_feat4[s1 * 16 + l]);
        float e0 = __expf(lrelu(a0 + adst));
        float e1 = __expf(lrelu(a1 + adst));
        acc.x = fmaf(e0, f0.x, fmaf(e1, f1.x, acc.x));
        acc.y = fmaf(e0, f0.y, fmaf(e1, f1.y, acc.y));
        acc.z = fmaf(e0, f0.z, fmaf(e1, f1.z, acc.z));
        acc.w = fmaf(e0, f0.w, fmaf(e1, f1.w, acc.w));
        den += e0 + e1;
    }
    if (j < end) {
        int s = __ldg(&g_srt[j]);
        float ex = __expf(lrelu(__ldg(&g_aux[s * 8 + h]) + adst));
        float4 f = __ldg(&g_feat4[s * 16 + l]);
        acc.x = fmaf(ex, f.x, acc.x);
        acc.y = fmaf(ex, f.y, acc.y);
        acc.z = fmaf(ex, f.z, acc.z);
        acc.w = fmaf(ex, f.w, acc.w);
        den += ex;
    }
    acc.x += __shfl_xor_sync(0xffffffffu, acc.x, 16);
    acc.y += __shfl_xor_sync(0xffffffffu, acc.y, 16);
    acc.z += __shfl_xor_sync(0xffffffffu, acc.z, 16);
    acc.w += __shfl_xor_sync(0xffffffffu, acc.w, 16);
    den   += __shfl_xor_sync(0xffffffffu, den, 16);
    if (half == 0) {
        float inv = 1.f / (den + 1e-16f);
        float4 bb = ((const float4*)b1)[l];
        float4 r;
        r.x = fmaxf(fmaf(acc.x, inv, bb.x), 0.f);
        r.y = fmaxf(fmaf(acc.y, inv, bb.y), 0.f);
        r.z = fmaxf(fmaf(acc.z, inv, bb.z), 0.f);
        r.w = fmaxf(fmaf(acc.w, inv, bb.w), 0.f);
        g_num4[node * 16 + l] = r;   // x1
    }
}

// GEMV: hl|hr = x1 @ [W2l|W2r] + bias
__global__ __launch_bounds__(256) void node1b_kernel(
    const float* __restrict__ W2l, const float* __restrict__ b2l,
    const float* __restrict__ W2r, const float* __restrict__ b2r, int n) {
    __shared__ float sx[256];               // 4 nodes * 64
    int t = threadIdx.x;
    int node = blockIdx.x * 4 + (t >> 6);
    int c = t & 63;
    bool valid = node < n;
    sx[t] = valid ? ((const float*)g_num4)[node * 64 + c] : 0.f;
    __syncthreads();
    if (!valid) return;
    const float* sxn = sx + (t & ~63);
    int col = c & 31;
    const float* W = (c < 32) ? W2l : W2r;
    float acc = (c < 32) ? b2l[col] : b2r[col];
    #pragma unroll 8
    for (int k = 0; k < 64; k++) acc = fmaf(sxn[k], W[k * 32 + col], acc);
    ((float*)g_feat4)[node * 64 + c] = acc;  // hl | hr
}

// ================= layer 2 =================
// warp per node; 8 lanes per edge (4 groups), unroll-2.
// In-loop shuffles use PER-GROUP masks (groups iterate different trip counts).
__global__ __launch_bounds__(256) void agg2_kernel(
    const float* __restrict__ att2, const float* __restrict__ b2, int n) {
    int node = (blockIdx.x * 256 + threadIdx.x) >> 5;
    if (node >= n) return;
    int lane = threadIdx.x & 31;
    int grp = lane >> 3;
    int l = lane & 7;
    unsigned gmask = 0xFFu << (grp * 8);
    float4 hr  = __ldg(&g_feat4[node * 16 + 8 + l]);
    float4 att = ((const float4*)att2)[l];
    int beg = g_off[node], end = g_off[node + 1];
    float4 acc = make_float4(0.f, 0.f, 0.f, 0.f);
    float den = 0.f;
    int j = beg + grp;
    for (; j + 4 < end; j += 8) {
        int s0 = __ldg(&g_srt[j]);
        int s1 = __ldg(&g_srt[j + 4]);
        float4 h0 = __ldg(&g_feat4[s0 * 16 + l]);
        float4 h1 = __ldg(&g_feat4[s1 * 16 + l]);
        float p0 = lrelu(h0.x + hr.x) * att.x + lrelu(h0.y + hr.y) * att.y
                 + lrelu(h0.z + hr.z) * att.z + lrelu(h0.w + hr.w) * att.w;
        float p1 = lrelu(h1.x + hr.x) * att.x + lrelu(h1.y + hr.y) * att.y
                 + lrelu(h1.z + hr.z) * att.z + lrelu(h1.w + hr.w) * att.w;
        p0 += __shfl_xor_sync(gmask, p0, 1);
        p0 += __shfl_xor_sync(gmask, p0, 2);
        p1 += __shfl_xor_sync(gmask, p1, 1);
        p1 += __shfl_xor_sync(gmask, p1, 2);
        float e0 = __expf(p0);
        float e1 = __expf(p1);
        acc.x = fmaf(e0, h0.x, fmaf(e1, h1.x, acc.x));
        acc.y = fmaf(e0, h0.y, fmaf(e1, h1.y, acc.y));
        acc.z = fmaf(e0, h0.z, fmaf(e1, h1.z, acc.z));
        acc.w = fmaf(e0, h0.w, fmaf(e1, h1.w, acc.w));
        den += e0 + e1;
    }
    if (j < end) {
        int s = __ldg(&g_srt[j]);
        float4 hl = __ldg(&g_feat4[s * 16 + l]);
        float p = lrelu(hl.x + hr.x) * att.x + lrelu(hl.y + hr.y) * att.y
                + lrelu(hl.z + hr.z) * att.z + lrelu(hl.w + hr.w) * att.w;
        p += __shfl_xor_sync(gmask, p, 1);
        p += __shfl_xor_sync(gmask, p, 2);
        float ex = __expf(p);
        acc.x = fmaf(ex, hl.x, acc.x);
        acc.y = fmaf(ex, hl.y, acc.y);
        acc.z = fmaf(ex, hl.z, acc.z);
        acc.w = fmaf(ex, hl.w, acc.w);
        den += ex;
    }
    #pragma unroll
    for (int o = 8; o <= 16; o <<= 1) {
        acc.x += __shfl_xor_sync(0xffffffffu, acc.x, o);
        acc.y += __shfl_xor_sync(0xffffffffu, acc.y, o);
        acc.z += __shfl_xor_sync(0xffffffffu, acc.z, o);
        acc.w += __shfl_xor_sync(0xffffffffu, acc.w, o);
        den   += __shfl_xor_sync(0xffffffffu, den, o);
    }
    if (grp == 0) {
        float inv = 1.f / (den + 1e-16f);
        float4 bb = ((const float4*)b2)[l];
        float4 r;
        r.x = fmaf(acc.x, inv, bb.x);
        r.y = fmaf(acc.y, inv, bb.y);
        r.z = fmaf(acc.z, inv, bb.z);
        r.w = fmaf(acc.w, inv, bb.w);
        g_num4[node * 16 + l] = r;   // x2 (32 floats)
    }
}

// GEMVs for layer 3: skip | q | k | v into feat row (offsets 0,8,16,24; pads zeroed)
__global__ __launch_bounds__(256) void node2_kernel(
    const float* __restrict__ Wq, const float* __restrict__ bq,
    const float* __restrict__ Wk, const float* __restrict__ bk,
    const float* __restrict__ Wv, const float* __restrict__ bv,
    const float* __restrict__ Ws, const float* __restrict__ bs, int n) {
    __shared__ float sx[256];               // 8 nodes * 32
    int t = threadIdx.x;
    int node = blockIdx.x * 8 + (t >> 5);
    int c = t & 31;
    bool valid = node < n;
    sx[t] = valid ? ((const float*)g_num4)[node * 64 + c] : 0.f;
    __syncthreads();
    if (!valid) return;
    const float* sxn = sx + (t & ~31);
    float* frow = ((float*)g_feat4) + (size_t)node * 64;
    if (c < 28) {
        int mat = c / 7, col = c % 7;
        const float* W; const float* b; int off;
        if (mat == 0)      { W = Ws; b = bs; off = 0;  }
        else if (mat == 1) { W = Wq; b = bq; off = 8;  }
        else if (mat == 2) { W = Wk; b = bk; off = 16; }
        else               { W = Wv; b = bv; off = 24; }
        float acc = b[col];
        #pragma unroll 8
        for (int k = 0; k < 32; k++) acc = fmaf(sxn[k], W[k * 7 + col], acc);
        frow[off + col] = acc;
    } else if (c == 28) {
        frow[7]  = 0.f;
        frow[15] = 0.f;
        frow[23] = 0.f;
        frow[31] = 0.f;
    }
}

// ================= layer 3 (fused final) =================
// warp per node; 8 lanes per edge (4 groups), unroll-2; skips self entry
__global__ __launch_bounds__(256) void agg3_kernel(float* __restrict__ out, int n) {
    int node = (blockIdx.x * 256 + threadIdx.x) >> 5;
    if (node >= n) return;
    int lane = threadIdx.x & 31;
    int grp = lane >> 3;
    int c = lane & 7;
    unsigned gmask = 0xFFu << (grp * 8);
    const float* frow = ((const float*)g_feat4) + (size_t)node * 64;
    float qv = __ldg(&frow[8 + c]);
    int beg = g_off[node] + 1;   // skip self (TransformerConv: no self-loops)
    int end = g_off[node + 1];
    float acc = 0.f, den = 0.f;
    int j = beg + grp;
    for (; j + 4 < end; j += 8) {
        int s0 = __ldg(&g_srt[j]);
        int s1 = __ldg(&g_srt[j + 4]);
        const float* f0 = ((const float*)g_feat4) + (size_t)s0 * 64;
        const float* f1 = ((const float*)g_feat4) + (size_t)s1 * 64;
        float k0 = __ldg(&f0[16 + c]);
        float k1 = __ldg(&f1[16 + c]);
        float v0 = __ldg(&f0[24 + c]);
        float v1 = __ldg(&f1[24 + c]);
        float p0 = qv * k0;
        float p1 = qv * k1;
        p0 += __shfl_xor_sync(gmask, p0, 1);
        p0 += __shfl_xor_sync(gmask, p0, 2);
        p0 += __shfl_xor_sync(gmask, p0, 4);
        p1 += __shfl_xor_sync(gmask, p1, 1);
        p1 += __shfl_xor_sync(gmask, p1, 2);
        p1 += __shfl_xor_sync(gmask, p1, 4);
        float e0 = __expf(p0 * 0.3779644730092272f);
        float e1 = __expf(p1 * 0.3779644730092272f);
        acc = fmaf(e0, v0, fmaf(e1, v1, acc));
        den += e0 + e1;
    }
    if (j < end) {
        int s = __ldg(&g_srt[j]);
        const float* fs = ((const float*)g_feat4) + (size_t)s * 64;
        float kv = __ldg(&fs[16 + c]);
        float vv = __ldg(&fs[24 + c]);
        float p = qv * kv;
        p += __shfl_xor_sync(gmask, p, 1);
        p += __shfl_xor_sync(gmask, p, 2);
        p += __shfl_xor_sync(gmask, p, 4);
        float ex = __expf(p * 0.3779644730092272f);
        acc = fmaf(ex, vv, acc);
        den += ex;
    }
    acc += __shfl_xor_sync(0xffffffffu, acc, 8);
    den += __shfl_xor_sync(0xffffffffu, den, 8);
    acc += __shfl_xor_sync(0xffffffffu, acc, 16);
    den += __shfl_xor_sync(0xffffffffu, den, 16);
    if (grp == 0 && c < 7)
        out[node * 7 + c] = acc / (den + 1e-16f) + frow[c];
}

// ================= launch =================

extern "C" void kernel_launch(void* const* d_in, const int* in_sizes, int n_in,
                              void* d_out, int out_size) {
    const float* x     = (const float*)d_in[0];
    const void*  eidx  = d_in[1];
    const float* W1    = (const float*)d_in[2];
    const float* asrc  = (const float*)d_in[3];
    const float* adst  = (const float*)d_in[4];
    const float* b1    = (const float*)d_in[5];
    const float* W2l   = (const float*)d_in[6];
    const float* b2l   = (const float*)d_in[7];
    const float* W2r   = (const float*)d_in[8];
    const float* b2r   = (const float*)d_in[9];
    const float* att2  = (const float*)d_in[10];
    const float* b2    = (const float*)d_in[11];
    const float* Wq    = (const float*)d_in[12];
    const float* bq    = (const float*)d_in[13];
    const float* Wk    = (const float*)d_in[14];
    const float* bk    = (const float*)d_in[15];
    const float* Wv    = (const float*)d_in[16];
    const float* bv    = (const float*)d_in[17];
    const float* Ws    = (const float*)d_in[18];
    const float* bs    = (const float*)d_in[19];
    float* out = (float*)d_out;

    int n = in_sizes[0] / 3;
    int e = in_sizes[1] / 2;
    if (n > NMAX) n = NMAX;
    if (e > EMAX) e = EMAX;
    int nb = (n + 1023) / 1024;

    // CSR build (g_cnt is zero here; scanC re-zeroes it for the next call)
    detect_kernel<<<1, 1>>>((const unsigned*)eidx, e);
    conv_hist_kernel<<<(e + 255) / 256, 256>>>(eidx, e);
    scanA_kernel<<<nb, 1024>>>(n);
    scanB_kernel<<<1, 128>>>(nb);
    scanC_kernel<<<nb, 1024>>>(n);
    scatter_kernel<<<(e + 255) / 256, 256>>>(e);

    int aggBlocks = (n * 32 + 255) / 256;
    // layer 1
    node1_kernel<<<(n * 64 + 255) / 256, 256>>>(x, W1, asrc, adst, n);
    agg1_kernel<<<aggBlocks, 256>>>(b1, n);
    node1b_kernel<<<(n + 3) / 4, 256>>>(W2l, b2l, W2r, b2r, n);
    // layer 2
    agg2_kernel<<<aggBlocks, 256>>>(att2, b2, n);
    node2_kernel<<<(n + 7) / 8, 256>>>(Wq, bq, Wk, bk, Wv, bv, Ws, bs, n);
    // layer 3 + final
    agg3_kernel<<<aggBlocks, 256>>>(out, n);
}

// round 5
// speedup vs baseline: 1.6608x; 1.3581x over previous
#include <cuda_runtime.h>

#define NMAX 100000
#define EMAX 1600000

// ---- scratch (device globals: no allocation allowed) ----
__device__ float4 g_feat4[NMAX * 16];     // per-node 64-float feature row
__device__ float4 g_num4[NMAX * 16];      // x1 (64f) then x2 (32f) storage
__device__ float  g_aux[NMAX * 8];        // layer1: a_src[4] | a_dst[4]
__device__ int    g_es[EMAX];             // raw src
__device__ int    g_ed[EMAX];             // raw dst
__device__ int    g_srt[EMAX + NMAX];     // CSR: in-neighbor src ids, self at head
__device__ int    g_cnt[NMAX];            // zero at entry; reset by scanC each call
__device__ int    g_off[NMAX + 1];
__device__ int    g_cur[NMAX];
__device__ int    g_part[256];
__device__ int    g_is64;

__device__ __forceinline__ float lrelu(float v) { return v > 0.f ? v : 0.2f * v; }

// ================= CSR construction =================

__global__ void detect_kernel(const unsigned* __restrict__ w, int e) {
    int cnt = e < 64 ? e : 64;
    int is64 = 1;
    for (int i = 0; i < cnt; i++)
        if (w[2 * i + 1] != 0u) { is64 = 0; break; }
    g_is64 = is64;
}

__global__ void conv_hist_kernel(const void* __restrict__ p, int e) {
    int i = blockIdx.x * blockDim.x + threadIdx.x;
    if (i >= e) return;
    int s, d;
    if (g_is64) {
        const long long* q = (const long long*)p;
        s = (int)q[i];
        d = (int)q[(long long)e + i];
    } else {
        const int* q = (const int*)p;
        s = q[i];
        d = q[e + i];
    }
    g_es[i] = s;
    g_ed[i] = d;
    atomicAdd(&g_cnt[d], 1);
}

__global__ void scanA_kernel(int n) {          // blockDim 1024: per-block sums
    __shared__ int sh[1024];
    int t = threadIdx.x;
    int i = blockIdx.x * 1024 + t;
    sh[t] = (i < n) ? g_cnt[i] + 1 : 0;        // +1: self-loop
    __syncthreads();
    for (int o = 512; o > 0; o >>= 1) {
        if (t < o) sh[t] += sh[t + o];
        __syncthreads();
    }
    if (t == 0) g_part[blockIdx.x] = sh[0];
}

__global__ void scanB_kernel(int nb) {         // 1 block, 128 threads: exclusive scan of partials
    __shared__ int sh[128];
    int t = threadIdx.x;
    int v = (t < nb) ? g_part[t] : 0;
    sh[t] = v;
    __syncthreads();
    #pragma unroll
    for (int o = 1; o < 128; o <<= 1) {
        int a = (t >= o) ? sh[t - o] : 0;
        __syncthreads();
        sh[t] += a;
        __syncthreads();
    }
    if (t < nb) g_part[t] = sh[t] - v;
}

__global__ void scanC_kernel(int n) {          // blockDim 1024: offsets + self at head + reset cnt
    __shared__ int sh[1024];
    int t = threadIdx.x;
    int i = blockIdx.x * 1024 + t;
    int v = (i < n) ? g_cnt[i] + 1 : 0;
    sh[t] = v;
    __syncthreads();
    for (int o = 1; o < 1024; o <<= 1) {
        int a = (t >= o) ? sh[t - o] : 0;
        __syncthreads();
        sh[t] += a;
        __syncthreads();
    }
    int excl = sh[t] - v + g_part[blockIdx.x];
    if (i < n) {
        g_off[i] = excl;
        g_cur[i] = excl + 1;
        g_srt[excl] = i;   // self at segment head
        g_cnt[i] = 0;      // leave zeroed for next call (deterministic across replays)
    }
    if (i == n - 1) g_off[n] = excl + v;
}

__global__ void scatter_kernel(int e) {
    int i = blockIdx.x * blockDim.x + threadIdx.x;
    if (i >= e) return;
    int d = g_ed[i];
    int pos = atomicAdd(&g_cur[d], 1);
    g_srt[pos] = g_es[i];
}

// ================= layer 1 =================

__global__ __launch_bounds__(256) void node1_kernel(
    const float* __restrict__ x, const float* __restrict__ W1,
    const float* __restrict__ asrc, const float* __restrict__ adst, int n) {
    int t = blockIdx.x * blockDim.x + threadIdx.x;
    int node = t >> 6;
    int c = t & 63;
    if (node >= n) return;
    float x0 = x[node * 3 + 0], x1 = x[node * 3 + 1], x2 = x[node * 3 + 2];
    float h = x0 * W1[c] + x1 * W1[64 + c] + x2 * W1[128 + c];
    ((float*)g_feat4)[node * 64 + c] = h;
    float ps = h * asrc[c];
    float pd = h * adst[c];
    #pragma unroll
    for (int o = 8; o >= 1; o >>= 1) {
        ps += __shfl_xor_sync(0xffffffffu, ps, o);
        pd += __shfl_xor_sync(0xffffffffu, pd, o);
    }
    if ((c & 15) == 0) {
        int hh = c >> 4;
        g_aux[node * 8 + hh]     = ps;
        g_aux[node * 8 + 4 + hh] = pd;
    }
}

// warp per node; 16 lanes per edge (2 groups), software-pipelined unroll-2
__global__ __launch_bounds__(256) void agg1_kernel(const float* __restrict__ b1, int n) {
    int node = (blockIdx.x * 256 + threadIdx.x) >> 5;
    if (node >= n) return;
    int lane = threadIdx.x & 31;
    int half = lane >> 4;
    int l = lane & 15;
    int h = l >> 2;
    float adst = g_aux[node * 8 + 4 + h];
    int beg = g_off[node], end = g_off[node + 1];
    float4 acc = make_float4(0.f, 0.f, 0.f, 0.f);
    float den = 0.f;
    int j = beg + half;
    for (; j + 2 < end; j += 4) {               // two independent edges per group
        int s0 = __ldg(&g_srt[j]);
        int s1 = __ldg(&g_srt[j + 2]);
        float a0 = __ldg(&g_aux[s0 * 8 + h]);
        float a1 = __ldg(&g_aux[s1 * 8 + h]);
        float4 f0 = __ldg(&g_feat4[s0 * 16 + l]);
        float4 f1 = __ldg(&g_feat4[s1 * 16 + l]);
        float e0 = __expf(lrelu(a0 + adst));
        float e1 = __expf(lrelu(a1 + adst));
        acc.x = fmaf(e0, f0.x, fmaf(e1, f1.x, acc.x));
        acc.y = fmaf(e0, f0.y, fmaf(e1, f1.y, acc.y));
        acc.z = fmaf(e0, f0.z, fmaf(e1, f1.z, acc.z));
        acc.w = fmaf(e0, f0.w, fmaf(e1, f1.w, acc.w));
        den += e0 + e1;
    }
    if (j < end) {
        int s = __ldg(&g_srt[j]);
        float ex = __expf(lrelu(__ldg(&g_aux[s * 8 + h]) + adst));
        float4 f = __ldg(&g_feat4[s * 16 + l]);
        acc.x = fmaf(ex, f.x, acc.x);
        acc.y = fmaf(ex, f.y, acc.y);
        acc.z = fmaf(ex, f.z, acc.z);
        acc.w = fmaf(ex, f.w, acc.w);
        den += ex;
    }
    acc.x += __shfl_xor_sync(0xffffffffu, acc.x, 16);
    acc.y += __shfl_xor_sync(0xffffffffu, acc.y, 16);
    acc.z += __shfl_xor_sync(0xffffffffu, acc.z, 16);
    acc.w += __shfl_xor_sync(0xffffffffu, acc.w, 16);
    den   += __shfl_xor_sync(0xffffffffu, den, 16);
    if (half == 0) {
        float inv = 1.f / (den + 1e-16f);
        float4 bb = ((const float4*)b1)[l];
        float4 r;
        r.x = fmaxf(fmaf(acc.x, inv, bb.x), 0.f);
        r.y = fmaxf(fmaf(acc.y, inv, bb.y), 0.f);
        r.z = fmaxf(fmaf(acc.z, inv, bb.z), 0.f);
        r.w = fmaxf(fmaf(acc.w, inv, bb.w), 0.f);
        g_num4[node * 16 + l] = r;   // x1
    }
}

// Register-tiled GEMV: hl|hr = x1 @ [W2l|W2r] + bias
// Block = 64 nodes. Warp owns 32 cols (half selects W2l/W2r); W column in regs.
__global__ __launch_bounds__(256) void gemv1_kernel(
    const float* __restrict__ W2l, const float* __restrict__ b2l,
    const float* __restrict__ W2r, const float* __restrict__ b2r, int n) {
    __shared__ float4 sx4[1024];   // 64 nodes * 64 floats
    int base = blockIdx.x * 64;
    int t = threadIdx.x;
    int lane = t & 31;
    int warpId = t >> 5;
    int half = warpId & 1;
    int lim = (n - base) * 16;     // valid float4 count in this tile
    #pragma unroll
    for (int i = 0; i < 4; i++) {
        int idx = t + i * 256;
        sx4[idx] = (idx < lim) ? g_num4[base * 16 + idx]
                               : make_float4(0.f, 0.f, 0.f, 0.f);
    }
    const float* Wsel = half ? W2r : W2l;
    float breg = half ? b2r[lane] : b2l[lane];
    float Wreg[64];
    #pragma unroll
    for (int k = 0; k < 64; k++) Wreg[k] = Wsel[k * 32 + lane];
    __syncthreads();
    int slot = warpId >> 1;
    for (int i = 0; i < 16; i++) {
        int nd = slot + i * 4;
        int node = base + nd;
        if (node >= n) break;                  // warp-uniform
        const float4* row = sx4 + nd * 16;
        float acc = breg;
        #pragma unroll
        for (int q = 0; q < 16; q++) {
            float4 v = row[q];                 // broadcast LDS.128
            acc = fmaf(Wreg[4 * q],     v.x, acc);
            acc = fmaf(Wreg[4 * q + 1], v.y, acc);
            acc = fmaf(Wreg[4 * q + 2], v.z, acc);
            acc = fmaf(Wreg[4 * q + 3], v.w, acc);
        }
        ((float*)g_feat4)[(size_t)node * 64 + half * 32 + lane] = acc;  // hl | hr
    }
}

// ================= layer 2 =================
// warp per node; 8 lanes per edge (4 groups), unroll-2.
__global__ __launch_bounds__(256) void agg2_kernel(
    const float* __restrict__ att2, const float* __restrict__ b2, int n) {
    int node = (blockIdx.x * 256 + threadIdx.x) >> 5;
    if (node >= n) return;
    int lane = threadIdx.x & 31;
    int grp = lane >> 3;
    int l = lane & 7;
    unsigned gmask = 0xFFu << (grp * 8);
    float4 hr  = __ldg(&g_feat4[node * 16 + 8 + l]);
    float4 att = ((const float4*)att2)[l];
    int beg = g_off[node], end = g_off[node + 1];
    float4 acc = make_float4(0.f, 0.f, 0.f, 0.f);
    float den = 0.f;
    int j = beg + grp;
    for (; j + 4 < end; j += 8) {
        int s0 = __ldg(&g_srt[j]);
        int s1 = __ldg(&g_srt[j + 4]);
        float4 h0 = __ldg(&g_feat4[s0 * 16 + l]);
        float4 h1 = __ldg(&g_feat4[s1 * 16 + l]);
        float p0 = lrelu(h0.x + hr.x) * att.x + lrelu(h0.y + hr.y) * att.y
                 + lrelu(h0.z + hr.z) * att.z + lrelu(h0.w + hr.w) * att.w;
        float p1 = lrelu(h1.x + hr.x) * att.x + lrelu(h1.y + hr.y) * att.y
                 + lrelu(h1.z + hr.z) * att.z + lrelu(h1.w + hr.w) * att.w;
        p0 += __shfl_xor_sync(gmask, p0, 1);
        p0 += __shfl_xor_sync(gmask, p0, 2);
        p1 += __shfl_xor_sync(gmask, p1, 1);
        p1 += __shfl_xor_sync(gmask, p1, 2);
        float e0 = __expf(p0);
        float e1 = __expf(p1);
        acc.x = fmaf(e0, h0.x, fmaf(e1, h1.x, acc.x));
        acc.y = fmaf(e0, h0.y, fmaf(e1, h1.y, acc.y));
        acc.z = fmaf(e0, h0.z, fmaf(e1, h1.z, acc.z));
        acc.w = fmaf(e0, h0.w, fmaf(e1, h1.w, acc.w));
        den += e0 + e1;
    }
    if (j < end) {
        int s = __ldg(&g_srt[j]);
        float4 hl = __ldg(&g_feat4[s * 16 + l]);
        float p = lrelu(hl.x + hr.x) * att.x + lrelu(hl.y + hr.y) * att.y
                + lrelu(hl.z + hr.z) * att.z + lrelu(hl.w + hr.w) * att.w;
        p += __shfl_xor_sync(gmask, p, 1);
        p += __shfl_xor_sync(gmask, p, 2);
        float ex = __expf(p);
        acc.x = fmaf(ex, hl.x, acc.x);
        acc.y = fmaf(ex, hl.y, acc.y);
        acc.z = fmaf(ex, hl.z, acc.z);
        acc.w = fmaf(ex, hl.w, acc.w);
        den += ex;
    }
    #pragma unroll
    for (int o = 8; o <= 16; o <<= 1) {
        acc.x += __shfl_xor_sync(0xffffffffu, acc.x, o);
        acc.y += __shfl_xor_sync(0xffffffffu, acc.y, o);
        acc.z += __shfl_xor_sync(0xffffffffu, acc.z, o);
        acc.w += __shfl_xor_sync(0xffffffffu, acc.w, o);
        den   += __shfl_xor_sync(0xffffffffu, den, o);
    }
    if (grp == 0) {
        float inv = 1.f / (den + 1e-16f);
        float4 bb = ((const float4*)b2)[l];
        float4 r;
        r.x = fmaf(acc.x, inv, bb.x);
        r.y = fmaf(acc.y, inv, bb.y);
        r.z = fmaf(acc.z, inv, bb.z);
        r.w = fmaf(acc.w, inv, bb.w);
        g_num4[node * 16 + l] = r;   // x2 (32 floats)
    }
}

// Register-tiled GEMVs for layer 3: skip|q|k|v -> g_feat4 row floats 0..31
// Lane = output slot (mat = lane>>3, col = lane&7; col 7 lanes write pad zeros).
__global__ __launch_bounds__(256) void gemv2_kernel(
    const float* __restrict__ Wq, const float* __restrict__ bq,
    const float* __restrict__ Wk, const float* __restrict__ bk,
    const float* __restrict__ Wv, const float* __restrict__ bv,
    const float* __restrict__ Ws, const float* __restrict__ bs, int n) {
    __shared__ float4 sx4[512];    // 64 nodes * 32 floats
    int base = blockIdx.x * 64;
    int t = threadIdx.x;
    int lane = t & 31;
    int warpId = t >> 5;
    #pragma unroll
    for (int i = 0; i < 2; i++) {
        int idx = t + i * 256;
        int nd = idx >> 3, j = idx & 7;
        int node = base + nd;
        sx4[idx] = (node < n) ? g_num4[node * 16 + j]
                              : make_float4(0.f, 0.f, 0.f, 0.f);
    }
    int mat = lane >> 3;
    int cc = lane & 7;
    bool pad = (cc == 7);
    const float* W  = (mat == 0) ? Ws : (mat == 1) ? Wq : (mat == 2) ? Wk : Wv;
    const float* bb = (mat == 0) ? bs : (mat == 1) ? bq : (mat == 2) ? bk : bv;
    float breg = pad ? 0.f : bb[cc];
    float Wreg[32];
    #pragma unroll
    for (int k = 0; k < 32; k++) Wreg[k] = pad ? 0.f : W[k * 7 + cc];
    __syncthreads();
    for (int i = 0; i < 8; i++) {
        int nd = warpId + i * 8;
        int node = base + nd;
        if (node >= n) break;                  // warp-uniform
        const float4* row = sx4 + nd * 8;
        float acc = breg;
        #pragma unroll
        for (int q = 0; q < 8; q++) {
            float4 v = row[q];
            acc = fmaf(Wreg[4 * q],     v.x, acc);
            acc = fmaf(Wreg[4 * q + 1], v.y, acc);
            acc = fmaf(Wreg[4 * q + 2], v.z, acc);
            acc = fmaf(Wreg[4 * q + 3], v.w, acc);
        }
        ((float*)g_feat4)[(size_t)node * 64 + lane] = acc;  // pads land as 0
    }
}

// ================= layer 3 (fused final) =================
// warp per node; 8 lanes per edge (4 groups), unroll-2; skips self entry
__global__ __launch_bounds__(256) void agg3_kernel(float* __restrict__ out, int n) {
    int node = (blockIdx.x * 256 + threadIdx.x) >> 5;
    if (node >= n) return;
    int lane = threadIdx.x & 31;
    int grp = lane >> 3;
    int c = lane & 7;
    unsigned gmask = 0xFFu << (grp * 8);
    const float* frow = ((const float*)g_feat4) + (size_t)node * 64;
    float qv = __ldg(&frow[8 + c]);
    int beg = g_off[node] + 1;   // skip self (TransformerConv: no self-loops)
    int end = g_off[node + 1];
    float acc = 0.f, den = 0.f;
    int j = beg + grp;
    for (; j + 4 < end; j += 8) {
        int s0 = __ldg(&g_srt[j]);
        int s1 = __ldg(&g_srt[j + 4]);
        const float* f0 = ((const float*)g_feat4) + (size_t)s0 * 64;
        const float* f1 = ((const float*)g_feat4) + (size_t)s1 * 64;
        float k0 = __ldg(&f0[16 + c]);
        float k1 = __ldg(&f1[16 + c]);
        float v0 = __ldg(&f0[24 + c]);
        float v1 = __ldg(&f1[24 + c]);
        float p0 = qv * k0;
        float p1 = qv * k1;
        p0 += __shfl_xor_sync(gmask, p0, 1);
        p0 += __shfl_xor_sync(gmask, p0, 2);
        p0 += __shfl_xor_sync(gmask, p0, 4);
        p1 += __shfl_xor_sync(gmask, p1, 1);
        p1 += __shfl_xor_sync(gmask, p1, 2);
        p1 += __shfl_xor_sync(gmask, p1, 4);
        float e0 = __expf(p0 * 0.3779644730092272f);
        float e1 = __expf(p1 * 0.3779644730092272f);
        acc = fmaf(e0, v0, fmaf(e1, v1, acc));
        den += e0 + e1;
    }
    if (j < end) {
        int s = __ldg(&g_srt[j]);
        const float* fs = ((const float*)g_feat4) + (size_t)s * 64;
        float kv = __ldg(&fs[16 + c]);
        float vv = __ldg(&fs[24 + c]);
        float p = qv * kv;
        p += __shfl_xor_sync(gmask, p, 1);
        p += __shfl_xor_sync(gmask, p, 2);
        p += __shfl_xor_sync(gmask, p, 4);
        float ex = __expf(p * 0.3779644730092272f);
        acc = fmaf(ex, vv, acc);
        den += ex;
    }
    acc += __shfl_xor_sync(0xffffffffu, acc, 8);
    den += __shfl_xor_sync(0xffffffffu, den, 8);
    acc += __shfl_xor_sync(0xffffffffu, acc, 16);
    den += __shfl_xor_sync(0xffffffffu, den, 16);
    if (grp == 0 && c < 7)
        out[node * 7 + c] = acc / (den + 1e-16f) + frow[c];
}

// ================= launch =================

extern "C" void kernel_launch(void* const* d_in, const int* in_sizes, int n_in,
                              void* d_out, int out_size) {
    const float* x     = (const float*)d_in[0];
    const void*  eidx  = d_in[1];
    const float* W1    = (const float*)d_in[2];
    const float* asrc  = (const float*)d_in[3];
    const float* adst  = (const float*)d_in[4];
    const float* b1    = (const float*)d_in[5];
    const float* W2l   = (const float*)d_in[6];
    const float* b2l   = (const float*)d_in[7];
    const float* W2r   = (const float*)d_in[8];
    const float* b2r   = (const float*)d_in[9];
    const float* att2  = (const float*)d_in[10];
    const float* b2    = (const float*)d_in[11];
    const float* Wq    = (const float*)d_in[12];
    const float* bq    = (const float*)d_in[13];
    const float* Wk    = (const float*)d_in[14];
    const float* bk    = (const float*)d_in[15];
    const float* Wv    = (const float*)d_in[16];
    const float* bv    = (const float*)d_in[17];
    const float* Ws    = (const float*)d_in[18];
    const float* bs    = (const float*)d_in[19];
    float* out = (float*)d_out;

    int n = in_sizes[0] / 3;
    int e = in_sizes[1] / 2;
    if (n > NMAX) n = NMAX;
    if (e > EMAX) e = EMAX;
    int nb = (n + 1023) / 1024;

    // CSR build
    detect_kernel<<<1, 1>>>((const unsigned*)eidx, e);
    conv_hist_kernel<<<(e + 255) / 256, 256>>>(eidx, e);
    scanA_kernel<<<nb, 1024>>>(n);
    scanB_kernel<<<1, 128>>>(nb);
    scanC_kernel<<<nb, 1024>>>(n);
    scatter_kernel<<<(e + 255) / 256, 256>>>(e);

    int aggBlocks = (n * 32 + 255) / 256;
    int tileBlocks = (n + 63) / 64;
    // layer 1
    node1_kernel<<<(n * 64 + 255) / 256, 256>>>(x, W1, asrc, adst, n);
    agg1_kernel<<<aggBlocks, 256>>>(b1, n);
    gemv1_kernel<<<tileBlocks, 256>>>(W2l, b2l, W2r, b2r, n);
    // layer 2
    agg2_kernel<<<aggBlocks, 256>>>(att2, b2, n);
    gemv2_kernel<<<tileBlocks, 256>>>(Wq, bq, Wk, bk, Wv, bv, Ws, bs, n);
    // layer 3 + final
    agg3_kernel<<<aggBlocks, 256>>>(out, n);
}